// round 2
// baseline (speedup 1.0000x reference)
#include <cuda_runtime.h>

// ---------------------------------------------------------------------------
// GCN_JK_Concat: 3x GCNConv(sym-norm, self-loops) + JK concat + Linear
// N=100000, E=1600000, F_IN=128, H=64, F_OUT=64
// edge_index arrives as int32 (JAX x64 disabled downcasts int64 -> int32).
// Strategy: build CSR-by-dst once (atomic counting + single-block scan +
// atomic fill), then each layer = tiled GEMM (transform) + warp-per-node
// gather (aggregate, bias, relu). Final layer = fused concat-GEMM reading
// x,h1,h2,h3 directly (no materialized concat).
// ---------------------------------------------------------------------------

#define NMAX   100000
#define EMAX   1600000
#define NNZMAX (EMAX + NMAX)

__device__ int   g_deg[NMAX];
__device__ float g_dis[NMAX];
__device__ int   g_rowptr[NMAX + 1];
__device__ int   g_cursor[NMAX];
__device__ int   g_col[NNZMAX];
__device__ float g_val[NNZMAX];
__device__ float g_hw[(size_t)NMAX * 64];
__device__ float g_h1[(size_t)NMAX * 64];
__device__ float g_h2[(size_t)NMAX * 64];
__device__ float g_h3[(size_t)NMAX * 64];

// ---------------------------------------------------------------------------
__global__ void k_init_deg(int n) {
    int i = blockIdx.x * blockDim.x + threadIdx.x;
    if (i < n) g_deg[i] = 1;   // self-loop
}

__global__ void k_count(const int* __restrict__ ei, int e) {
    int i = blockIdx.x * blockDim.x + threadIdx.x;
    if (i < e) {
        int d = ei[(size_t)e + i];   // row 1 = dst
        atomicAdd(&g_deg[d], 1);
    }
}

// Single-block inclusive scan over degrees -> rowptr/cursor, plus dis=rsqrt(deg)
__global__ void __launch_bounds__(1024) k_scan(int n) {
    __shared__ int warpsum[32];
    __shared__ int s_carry;
    int t = threadIdx.x;
    int lane = t & 31;
    int w = t >> 5;
    if (t == 0) s_carry = 0;
    __syncthreads();
    int nchunk = (n + 1023) >> 10;
    for (int c = 0; c < nchunk; c++) {
        int i = (c << 10) + t;
        int v = (i < n) ? g_deg[i] : 0;
        int s = v;
        #pragma unroll
        for (int o = 1; o < 32; o <<= 1) {
            int x = __shfl_up_sync(0xffffffffu, s, o);
            if (lane >= o) s += x;
        }
        if (lane == 31) warpsum[w] = s;
        __syncthreads();
        if (w == 0) {
            int v2 = warpsum[lane];
            #pragma unroll
            for (int o = 1; o < 32; o <<= 1) {
                int x = __shfl_up_sync(0xffffffffu, v2, o);
                if (lane >= o) v2 += x;
            }
            warpsum[lane] = v2;
        }
        __syncthreads();
        int prefix = (w == 0) ? 0 : warpsum[w - 1];
        int incl = prefix + s;          // inclusive within chunk
        int ex = incl - v;              // exclusive within chunk
        int carry = s_carry;
        if (i < n) {
            int rp = carry + ex;
            g_rowptr[i] = rp;
            g_cursor[i] = rp;
            g_dis[i] = rsqrtf((float)v);
        }
        __syncthreads();
        if (t == 1023) s_carry = carry + incl;
        __syncthreads();
    }
    if (t == 0) g_rowptr[n] = s_carry;
}

__global__ void k_fill(const int* __restrict__ ei, int e, int n) {
    int i = blockIdx.x * blockDim.x + threadIdx.x;
    int s, d;
    if (i < e) {
        s = ei[i];
        d = ei[(size_t)e + i];
    } else if (i < e + n) {
        s = d = i - e;                  // self-loop
    } else {
        return;
    }
    int pos = atomicAdd(&g_cursor[d], 1);
    g_col[pos] = s;
    g_val[pos] = g_dis[s] * g_dis[d];
}

// ---------------------------------------------------------------------------
// Tiled GEMM: out[n,64] = A[n,K] @ W[K,64].  64 rows/block, 256 threads,
// 4x4 register tile per thread, K chunked by 64 through shared memory.
// ---------------------------------------------------------------------------
#define GR  64
#define GKC 64

__global__ void __launch_bounds__(256) k_gemm(
    const float* __restrict__ A, int K,
    const float* __restrict__ W,
    float* __restrict__ out, int n)
{
    __shared__ float xs[GR][GKC + 1];
    __shared__ float ws[GKC][64];
    int t = threadIdx.x;
    int tx = t & 15, ty = t >> 4;
    int rowBase = blockIdx.x * GR;
    float acc[4][4] = {};

    for (int kk = 0; kk < K; kk += GKC) {
        #pragma unroll
        for (int s = 0; s < 4; s++) {
            int slot = t + s * 256;           // 0..1023
            int r = slot >> 4;
            int k4 = slot & 15;
            int row = rowBase + r;
            float4 v = make_float4(0.f, 0.f, 0.f, 0.f);
            if (row < n) v = *(const float4*)&A[(size_t)row * K + kk + k4 * 4];
            xs[r][k4 * 4 + 0] = v.x;
            xs[r][k4 * 4 + 1] = v.y;
            xs[r][k4 * 4 + 2] = v.z;
            xs[r][k4 * 4 + 3] = v.w;
        }
        #pragma unroll
        for (int s = 0; s < 4; s++) {
            int slot = t + s * 256;
            int k = slot >> 4;
            int c4 = slot & 15;
            *(float4*)&ws[k][c4 * 4] = *(const float4*)&W[(size_t)(kk + k) * 64 + c4 * 4];
        }
        __syncthreads();
        #pragma unroll 8
        for (int k = 0; k < GKC; k++) {
            float a0 = xs[4 * ty + 0][k];
            float a1 = xs[4 * ty + 1][k];
            float a2 = xs[4 * ty + 2][k];
            float a3 = xs[4 * ty + 3][k];
            float4 wv = *(const float4*)&ws[k][4 * tx];
            acc[0][0] = fmaf(a0, wv.x, acc[0][0]); acc[0][1] = fmaf(a0, wv.y, acc[0][1]);
            acc[0][2] = fmaf(a0, wv.z, acc[0][2]); acc[0][3] = fmaf(a0, wv.w, acc[0][3]);
            acc[1][0] = fmaf(a1, wv.x, acc[1][0]); acc[1][1] = fmaf(a1, wv.y, acc[1][1]);
            acc[1][2] = fmaf(a1, wv.z, acc[1][2]); acc[1][3] = fmaf(a1, wv.w, acc[1][3]);
            acc[2][0] = fmaf(a2, wv.x, acc[2][0]); acc[2][1] = fmaf(a2, wv.y, acc[2][1]);
            acc[2][2] = fmaf(a2, wv.z, acc[2][2]); acc[2][3] = fmaf(a2, wv.w, acc[2][3]);
            acc[3][0] = fmaf(a3, wv.x, acc[3][0]); acc[3][1] = fmaf(a3, wv.y, acc[3][1]);
            acc[3][2] = fmaf(a3, wv.z, acc[3][2]); acc[3][3] = fmaf(a3, wv.w, acc[3][3]);
        }
        __syncthreads();
    }
    #pragma unroll
    for (int i = 0; i < 4; i++) {
        int row = rowBase + 4 * ty + i;
        if (row < n)
            *(float4*)&out[(size_t)row * 64 + 4 * tx] =
                make_float4(acc[i][0], acc[i][1], acc[i][2], acc[i][3]);
    }
}

// ---------------------------------------------------------------------------
// Final GEMM on virtual concat [x | h1 | h2 | h3] (K=320) with bias.
// ---------------------------------------------------------------------------
__global__ void __launch_bounds__(256) k_gemm_cat(
    const float* __restrict__ x,
    const float* __restrict__ Wl,
    const float* __restrict__ bl,
    float* __restrict__ out, int n)
{
    __shared__ float xs[GR][GKC + 1];
    __shared__ float ws[GKC][64];
    int t = threadIdx.x;
    int tx = t & 15, ty = t >> 4;
    int rowBase = blockIdx.x * GR;
    float acc[4][4] = {};

    for (int kk = 0; kk < 320; kk += GKC) {
        const float* src;
        int stride, koff;
        if (kk < 128)      { src = x;    stride = 128; koff = kk; }
        else if (kk < 192) { src = g_h1; stride = 64;  koff = 0; }
        else if (kk < 256) { src = g_h2; stride = 64;  koff = 0; }
        else               { src = g_h3; stride = 64;  koff = 0; }

        #pragma unroll
        for (int s = 0; s < 4; s++) {
            int slot = t + s * 256;
            int r = slot >> 4;
            int k4 = slot & 15;
            int row = rowBase + r;
            float4 v = make_float4(0.f, 0.f, 0.f, 0.f);
            if (row < n) v = *(const float4*)&src[(size_t)row * stride + koff + k4 * 4];
            xs[r][k4 * 4 + 0] = v.x;
            xs[r][k4 * 4 + 1] = v.y;
            xs[r][k4 * 4 + 2] = v.z;
            xs[r][k4 * 4 + 3] = v.w;
        }
        #pragma unroll
        for (int s = 0; s < 4; s++) {
            int slot = t + s * 256;
            int k = slot >> 4;
            int c4 = slot & 15;
            *(float4*)&ws[k][c4 * 4] = *(const float4*)&Wl[(size_t)(kk + k) * 64 + c4 * 4];
        }
        __syncthreads();
        #pragma unroll 8
        for (int k = 0; k < GKC; k++) {
            float a0 = xs[4 * ty + 0][k];
            float a1 = xs[4 * ty + 1][k];
            float a2 = xs[4 * ty + 2][k];
            float a3 = xs[4 * ty + 3][k];
            float4 wv = *(const float4*)&ws[k][4 * tx];
            acc[0][0] = fmaf(a0, wv.x, acc[0][0]); acc[0][1] = fmaf(a0, wv.y, acc[0][1]);
            acc[0][2] = fmaf(a0, wv.z, acc[0][2]); acc[0][3] = fmaf(a0, wv.w, acc[0][3]);
            acc[1][0] = fmaf(a1, wv.x, acc[1][0]); acc[1][1] = fmaf(a1, wv.y, acc[1][1]);
            acc[1][2] = fmaf(a1, wv.z, acc[1][2]); acc[1][3] = fmaf(a1, wv.w, acc[1][3]);
            acc[2][0] = fmaf(a2, wv.x, acc[2][0]); acc[2][1] = fmaf(a2, wv.y, acc[2][1]);
            acc[2][2] = fmaf(a2, wv.z, acc[2][2]); acc[2][3] = fmaf(a2, wv.w, acc[2][3]);
            acc[3][0] = fmaf(a3, wv.x, acc[3][0]); acc[3][1] = fmaf(a3, wv.y, acc[3][1]);
            acc[3][2] = fmaf(a3, wv.z, acc[3][2]); acc[3][3] = fmaf(a3, wv.w, acc[3][3]);
        }
        __syncthreads();
    }
    float4 bv = *(const float4*)&bl[4 * tx];
    #pragma unroll
    for (int i = 0; i < 4; i++) {
        int row = rowBase + 4 * ty + i;
        if (row < n)
            *(float4*)&out[(size_t)row * 64 + 4 * tx] =
                make_float4(acc[i][0] + bv.x, acc[i][1] + bv.y,
                            acc[i][2] + bv.z, acc[i][3] + bv.w);
    }
}

// ---------------------------------------------------------------------------
// Aggregation: warp per node, lane handles 2 of 64 feature columns.
// hout[node] = relu(bias + sum_e val[e] * hw[col[e]])
// ---------------------------------------------------------------------------
__global__ void __launch_bounds__(256) k_gather(
    const float* __restrict__ hw,
    const float* __restrict__ bias,
    float* __restrict__ hout, int n)
{
    int g = blockIdx.x * blockDim.x + threadIdx.x;
    int node = g >> 5;
    int lane = g & 31;
    if (node >= n) return;
    int beg = g_rowptr[node];
    int end = g_rowptr[node + 1];
    float a0 = 0.f, a1 = 0.f;
    int e = beg;
    for (; e + 1 < end; e += 2) {
        int   c0 = __ldg(&g_col[e]);
        int   c1 = __ldg(&g_col[e + 1]);
        float v0 = __ldg(&g_val[e]);
        float v1 = __ldg(&g_val[e + 1]);
        float2 f0 = *(const float2*)&hw[(size_t)c0 * 64 + 2 * lane];
        float2 f1 = *(const float2*)&hw[(size_t)c1 * 64 + 2 * lane];
        a0 = fmaf(v0, f0.x, a0); a1 = fmaf(v0, f0.y, a1);
        a0 = fmaf(v1, f1.x, a0); a1 = fmaf(v1, f1.y, a1);
    }
    if (e < end) {
        int   c0 = __ldg(&g_col[e]);
        float v0 = __ldg(&g_val[e]);
        float2 f0 = *(const float2*)&hw[(size_t)c0 * 64 + 2 * lane];
        a0 = fmaf(v0, f0.x, a0); a1 = fmaf(v0, f0.y, a1);
    }
    float2 o;
    o.x = fmaxf(a0 + bias[2 * lane], 0.f);
    o.y = fmaxf(a1 + bias[2 * lane + 1], 0.f);
    *(float2*)&hout[(size_t)node * 64 + 2 * lane] = o;
}

// ---------------------------------------------------------------------------
extern "C" void kernel_launch(void* const* d_in, const int* in_sizes, int n_in,
                              void* d_out, int out_size)
{
    const float* x  = (const float*)d_in[0];
    const int*   ei = (const int*)d_in[1];     // int32 edge_index [2, E]
    const float* W0 = (const float*)d_in[2];
    const float* b0 = (const float*)d_in[3];
    const float* W1 = (const float*)d_in[4];
    const float* b1 = (const float*)d_in[5];
    const float* W2 = (const float*)d_in[6];
    const float* b2 = (const float*)d_in[7];
    const float* Wl = (const float*)d_in[8];
    const float* bl = (const float*)d_in[9];
    float* out = (float*)d_out;

    int n = in_sizes[0] / 128;
    int e = in_sizes[1] / 2;

    float* hw_ptr = nullptr;
    float* h1_ptr = nullptr;
    float* h2_ptr = nullptr;
    float* h3_ptr = nullptr;
    cudaGetSymbolAddress((void**)&hw_ptr, g_hw);
    cudaGetSymbolAddress((void**)&h1_ptr, g_h1);
    cudaGetSymbolAddress((void**)&h2_ptr, g_h2);
    cudaGetSymbolAddress((void**)&h3_ptr, g_h3);

    // ---- CSR build ----
    k_init_deg<<<(n + 255) / 256, 256>>>(n);
    k_count<<<(e + 255) / 256, 256>>>(ei, e);
    k_scan<<<1, 1024>>>(n);
    k_fill<<<(e + n + 255) / 256, 256>>>(ei, e, n);

    int gemm_blocks = (n + GR - 1) / GR;
    int gather_blocks = (n * 32 + 255) / 256;

    // ---- layer 1 ----
    k_gemm<<<gemm_blocks, 256>>>(x, 128, W0, hw_ptr, n);
    k_gather<<<gather_blocks, 256>>>(hw_ptr, b0, h1_ptr, n);
    // ---- layer 2 ----
    k_gemm<<<gemm_blocks, 256>>>(h1_ptr, 64, W1, hw_ptr, n);
    k_gather<<<gather_blocks, 256>>>(hw_ptr, b1, h2_ptr, n);
    // ---- layer 3 ----
    k_gemm<<<gemm_blocks, 256>>>(h2_ptr, 64, W2, hw_ptr, n);
    k_gather<<<gather_blocks, 256>>>(hw_ptr, b2, h3_ptr, n);
    // ---- JK concat + linear ----
    k_gemm_cat<<<gemm_blocks, 256>>>(x, Wl, bl, out, n);
}

// round 3
// speedup vs baseline: 1.2127x; 1.2127x over previous
#include <cuda_runtime.h>

// ---------------------------------------------------------------------------
// GCN_JK_Concat: 3x GCNConv(sym-norm, self-loops) + JK concat + Linear
// N=100000, E=1600000, F_IN=128, H=64, F_OUT=64
// R3: parallel 3-pass scan; GEMMs rebuilt as 128x64 tiles with 8x8 register
// tiles and packed fma.rn.f32x2 (Blackwell FFMA2, 2 FLOP/issue).
// ---------------------------------------------------------------------------

#define NMAX   100000
#define EMAX   1600000
#define NNZMAX (EMAX + NMAX)
#define NBSCAN 128   // max scan blocks (ceil(100000/1024)=98)

__device__ int   g_deg[NMAX];
__device__ float g_dis[NMAX];
__device__ int   g_rowptr[NMAX + 1];
__device__ int   g_cursor[NMAX];
__device__ int   g_bsum[NBSCAN];
__device__ int   g_boff[NBSCAN];
__device__ int   g_col[NNZMAX];
__device__ float g_val[NNZMAX];
__device__ float g_hw[(size_t)NMAX * 64];
__device__ float g_h1[(size_t)NMAX * 64];
__device__ float g_h2[(size_t)NMAX * 64];
__device__ float g_h3[(size_t)NMAX * 64];

// ---------------------------------------------------------------------------
__global__ void k_init_deg(int n) {
    int i = blockIdx.x * blockDim.x + threadIdx.x;
    if (i < n) g_deg[i] = 1;   // self-loop
}

__global__ void k_count(const int* __restrict__ ei, int e) {
    int i = blockIdx.x * blockDim.x + threadIdx.x;
    if (i < e) {
        int d = ei[(size_t)e + i];   // row 1 = dst
        atomicAdd(&g_deg[d], 1);
    }
}

// ---- 3-pass parallel scan ----
__global__ void __launch_bounds__(1024) k_scan_local(int n) {
    __shared__ int warpsum[32];
    int t = threadIdx.x;
    int lane = t & 31;
    int w = t >> 5;
    int i = blockIdx.x * 1024 + t;
    int v = (i < n) ? g_deg[i] : 0;
    int s = v;
    #pragma unroll
    for (int o = 1; o < 32; o <<= 1) {
        int x = __shfl_up_sync(0xffffffffu, s, o);
        if (lane >= o) s += x;
    }
    if (lane == 31) warpsum[w] = s;
    __syncthreads();
    if (w == 0) {
        int v2 = warpsum[lane];
        #pragma unroll
        for (int o = 1; o < 32; o <<= 1) {
            int x = __shfl_up_sync(0xffffffffu, v2, o);
            if (lane >= o) v2 += x;
        }
        warpsum[lane] = v2;
    }
    __syncthreads();
    int prefix = (w == 0) ? 0 : warpsum[w - 1];
    int incl = prefix + s;
    if (i < n) {
        g_rowptr[i] = incl - v;          // local exclusive
        g_dis[i] = rsqrtf((float)v);
    }
    if (t == 1023) g_bsum[blockIdx.x] = incl;  // block total
}

__global__ void __launch_bounds__(128) k_scan_bsums(int nb, int n) {
    int t = threadIdx.x;
    int lane = t & 31;
    int w = t >> 5;
    __shared__ int warpsum[4];
    int v = (t < nb) ? g_bsum[t] : 0;
    int s = v;
    #pragma unroll
    for (int o = 1; o < 32; o <<= 1) {
        int x = __shfl_up_sync(0xffffffffu, s, o);
        if (lane >= o) s += x;
    }
    if (lane == 31) warpsum[w] = s;
    __syncthreads();
    int pre = 0;
    for (int j = 0; j < w; j++) pre += warpsum[j];
    if (t < nb) g_boff[t] = pre + s - v;   // exclusive
    if (t == nb - 1) g_rowptr[n] = pre + s;
}

__global__ void __launch_bounds__(1024) k_scan_add(int n) {
    int i = blockIdx.x * 1024 + threadIdx.x;
    if (i < n) {
        int rp = g_rowptr[i] + g_boff[blockIdx.x];
        g_rowptr[i] = rp;
        g_cursor[i] = rp;
    }
}

__global__ void k_fill(const int* __restrict__ ei, int e, int n) {
    int i = blockIdx.x * blockDim.x + threadIdx.x;
    int s, d;
    if (i < e) {
        s = ei[i];
        d = ei[(size_t)e + i];
    } else if (i < e + n) {
        s = d = i - e;                  // self-loop
    } else {
        return;
    }
    int pos = atomicAdd(&g_cursor[d], 1);
    g_col[pos] = s;
    g_val[pos] = g_dis[s] * g_dis[d];
}

// ---------------------------------------------------------------------------
// GEMM v2: out[n,64] = A[n,K] @ W[K,64].
// 128 rows/block, 128 threads, 8x8 register tile, K chunked by 32.
// Packed fp32x2 FMA (Blackwell FFMA2).
// ---------------------------------------------------------------------------
#define TR2 128
#define TK2 32

#define FMA2(acc, a, b) \
    asm("fma.rn.f32x2 %0, %1, %2, %0;" : "+l"(acc) : "l"(a), "l"(b))

__device__ __forceinline__ unsigned long long bcast2(float a) {
    unsigned long long r;
    asm("mov.b64 %0, {%1, %1};" : "=l"(r) : "f"(a));
    return r;
}

// core compute shared by both GEMMs; xs/ws in smem, acc in caller regs
struct GemmSmem {
    float xs[TR2][TK2 + 5];   // stride 37: conflict-free scalar reads
    float ws[TK2][64 + 4];    // stride 68: aligned LDS.128, broadcast
};

__device__ __forceinline__ void gemm_tile_load_W(
    GemmSmem* sm, const float* __restrict__ W, int kk, int t)
{
    #pragma unroll
    for (int s = 0; s < 4; s++) {
        int slot = t + s * 128;          // 0..511
        int k = slot >> 4;
        int c4 = slot & 15;
        *(float4*)&sm->ws[k][c4 * 4] = *(const float4*)&W[(size_t)(kk + k) * 64 + c4 * 4];
    }
}

__device__ __forceinline__ void gemm_tile_compute(
    GemmSmem* sm, int tx, int ty, unsigned long long acc[8][4])
{
    #pragma unroll
    for (int k = 0; k < TK2; k++) {
        ulonglong2 wA = *(const ulonglong2*)&sm->ws[k][8 * tx];
        ulonglong2 wB = *(const ulonglong2*)&sm->ws[k][8 * tx + 4];
        #pragma unroll
        for (int i = 0; i < 8; i++) {
            unsigned long long aa = bcast2(sm->xs[8 * ty + i][k]);
            FMA2(acc[i][0], aa, wA.x);
            FMA2(acc[i][1], aa, wA.y);
            FMA2(acc[i][2], aa, wB.x);
            FMA2(acc[i][3], aa, wB.y);
        }
    }
}

__global__ void __launch_bounds__(128) k_gemm2(
    const float* __restrict__ A, int K,
    const float* __restrict__ W,
    float* __restrict__ out, int n)
{
    __shared__ GemmSmem sm;
    int t = threadIdx.x;
    int tx = t & 7, ty = t >> 3;
    int rowBase = blockIdx.x * TR2;
    unsigned long long acc[8][4] = {};

    for (int kk = 0; kk < K; kk += TK2) {
        #pragma unroll
        for (int s = 0; s < 8; s++) {
            int slot = t + s * 128;       // 0..1023
            int r = slot >> 3;
            int k4 = slot & 7;
            int row = rowBase + r;
            float4 v = make_float4(0.f, 0.f, 0.f, 0.f);
            if (row < n) v = *(const float4*)&A[(size_t)row * K + kk + k4 * 4];
            sm.xs[r][k4 * 4 + 0] = v.x;
            sm.xs[r][k4 * 4 + 1] = v.y;
            sm.xs[r][k4 * 4 + 2] = v.z;
            sm.xs[r][k4 * 4 + 3] = v.w;
        }
        gemm_tile_load_W(&sm, W, kk, t);
        __syncthreads();
        gemm_tile_compute(&sm, tx, ty, acc);
        __syncthreads();
    }
    #pragma unroll
    for (int i = 0; i < 8; i++) {
        int row = rowBase + 8 * ty + i;
        if (row < n) {
            float2 f0 = *(float2*)&acc[i][0];
            float2 f1 = *(float2*)&acc[i][1];
            float2 f2 = *(float2*)&acc[i][2];
            float2 f3 = *(float2*)&acc[i][3];
            *(float4*)&out[(size_t)row * 64 + 8 * tx]     = make_float4(f0.x, f0.y, f1.x, f1.y);
            *(float4*)&out[(size_t)row * 64 + 8 * tx + 4] = make_float4(f2.x, f2.y, f3.x, f3.y);
        }
    }
}

// Final GEMM on virtual concat [x | h1 | h2 | h3] (K=320) with bias.
__global__ void __launch_bounds__(128) k_gemm_cat2(
    const float* __restrict__ x,
    const float* __restrict__ Wl,
    const float* __restrict__ bl,
    float* __restrict__ out, int n)
{
    __shared__ GemmSmem sm;
    int t = threadIdx.x;
    int tx = t & 7, ty = t >> 3;
    int rowBase = blockIdx.x * TR2;
    unsigned long long acc[8][4] = {};

    for (int kk = 0; kk < 320; kk += TK2) {
        const float* src;
        int stride, koff;
        if (kk < 128)      { src = x;    stride = 128; koff = kk; }
        else if (kk < 192) { src = g_h1; stride = 64;  koff = kk - 128; }
        else if (kk < 256) { src = g_h2; stride = 64;  koff = kk - 192; }
        else               { src = g_h3; stride = 64;  koff = kk - 256; }

        #pragma unroll
        for (int s = 0; s < 8; s++) {
            int slot = t + s * 128;
            int r = slot >> 3;
            int k4 = slot & 7;
            int row = rowBase + r;
            float4 v = make_float4(0.f, 0.f, 0.f, 0.f);
            if (row < n) v = *(const float4*)&src[(size_t)row * stride + koff + k4 * 4];
            sm.xs[r][k4 * 4 + 0] = v.x;
            sm.xs[r][k4 * 4 + 1] = v.y;
            sm.xs[r][k4 * 4 + 2] = v.z;
            sm.xs[r][k4 * 4 + 3] = v.w;
        }
        gemm_tile_load_W(&sm, Wl, kk, t);
        __syncthreads();
        gemm_tile_compute(&sm, tx, ty, acc);
        __syncthreads();
    }
    float4 bv0 = *(const float4*)&bl[8 * tx];
    float4 bv1 = *(const float4*)&bl[8 * tx + 4];
    #pragma unroll
    for (int i = 0; i < 8; i++) {
        int row = rowBase + 8 * ty + i;
        if (row < n) {
            float2 f0 = *(float2*)&acc[i][0];
            float2 f1 = *(float2*)&acc[i][1];
            float2 f2 = *(float2*)&acc[i][2];
            float2 f3 = *(float2*)&acc[i][3];
            *(float4*)&out[(size_t)row * 64 + 8 * tx] =
                make_float4(f0.x + bv0.x, f0.y + bv0.y, f1.x + bv0.z, f1.y + bv0.w);
            *(float4*)&out[(size_t)row * 64 + 8 * tx + 4] =
                make_float4(f2.x + bv1.x, f2.y + bv1.y, f3.x + bv1.z, f3.y + bv1.w);
        }
    }
}

// ---------------------------------------------------------------------------
// Aggregation: warp per node, lane handles 2 of 64 feature columns.
// hout[node] = relu(bias + sum_e val[e] * hw[col[e]])
// ---------------------------------------------------------------------------
__global__ void __launch_bounds__(256) k_gather(
    const float* __restrict__ hw,
    const float* __restrict__ bias,
    float* __restrict__ hout, int n)
{
    int g = blockIdx.x * blockDim.x + threadIdx.x;
    int node = g >> 5;
    int lane = g & 31;
    if (node >= n) return;
    int beg = g_rowptr[node];
    int end = g_rowptr[node + 1];
    float a0 = 0.f, a1 = 0.f;
    int e = beg;
    for (; e + 1 < end; e += 2) {
        int   c0 = __ldg(&g_col[e]);
        int   c1 = __ldg(&g_col[e + 1]);
        float v0 = __ldg(&g_val[e]);
        float v1 = __ldg(&g_val[e + 1]);
        float2 f0 = *(const float2*)&hw[(size_t)c0 * 64 + 2 * lane];
        float2 f1 = *(const float2*)&hw[(size_t)c1 * 64 + 2 * lane];
        a0 = fmaf(v0, f0.x, a0); a1 = fmaf(v0, f0.y, a1);
        a0 = fmaf(v1, f1.x, a0); a1 = fmaf(v1, f1.y, a1);
    }
    if (e < end) {
        int   c0 = __ldg(&g_col[e]);
        float v0 = __ldg(&g_val[e]);
        float2 f0 = *(const float2*)&hw[(size_t)c0 * 64 + 2 * lane];
        a0 = fmaf(v0, f0.x, a0); a1 = fmaf(v0, f0.y, a1);
    }
    float2 o;
    o.x = fmaxf(a0 + bias[2 * lane], 0.f);
    o.y = fmaxf(a1 + bias[2 * lane + 1], 0.f);
    *(float2*)&hout[(size_t)node * 64 + 2 * lane] = o;
}

// ---------------------------------------------------------------------------
extern "C" void kernel_launch(void* const* d_in, const int* in_sizes, int n_in,
                              void* d_out, int out_size)
{
    const float* x  = (const float*)d_in[0];
    const int*   ei = (const int*)d_in[1];     // int32 edge_index [2, E]
    const float* W0 = (const float*)d_in[2];
    const float* b0 = (const float*)d_in[3];
    const float* W1 = (const float*)d_in[4];
    const float* b1 = (const float*)d_in[5];
    const float* W2 = (const float*)d_in[6];
    const float* b2 = (const float*)d_in[7];
    const float* Wl = (const float*)d_in[8];
    const float* bl = (const float*)d_in[9];
    float* out = (float*)d_out;

    int n = in_sizes[0] / 128;
    int e = in_sizes[1] / 2;
    int nb = (n + 1023) >> 10;

    float* hw_ptr = nullptr;
    float* h1_ptr = nullptr;
    float* h2_ptr = nullptr;
    float* h3_ptr = nullptr;
    cudaGetSymbolAddress((void**)&hw_ptr, g_hw);
    cudaGetSymbolAddress((void**)&h1_ptr, g_h1);
    cudaGetSymbolAddress((void**)&h2_ptr, g_h2);
    cudaGetSymbolAddress((void**)&h3_ptr, g_h3);

    // ---- CSR build ----
    k_init_deg<<<(n + 255) / 256, 256>>>(n);
    k_count<<<(e + 255) / 256, 256>>>(ei, e);
    k_scan_local<<<nb, 1024>>>(n);
    k_scan_bsums<<<1, 128>>>(nb, n);
    k_scan_add<<<nb, 1024>>>(n);
    k_fill<<<(e + n + 255) / 256, 256>>>(ei, e, n);

    int gemm_blocks = (n + TR2 - 1) / TR2;
    int gather_blocks = (n * 32 + 255) / 256;

    // ---- layer 1 ----
    k_gemm2<<<gemm_blocks, 128>>>(x, 128, W0, hw_ptr, n);
    k_gather<<<gather_blocks, 256>>>(hw_ptr, b0, h1_ptr, n);
    // ---- layer 2 ----
    k_gemm2<<<gemm_blocks, 128>>>(h1_ptr, 64, W1, hw_ptr, n);
    k_gather<<<gather_blocks, 256>>>(hw_ptr, b1, h2_ptr, n);
    // ---- layer 3 ----
    k_gemm2<<<gemm_blocks, 128>>>(h2_ptr, 64, W2, hw_ptr, n);
    k_gather<<<gather_blocks, 256>>>(hw_ptr, b2, h3_ptr, n);
    // ---- JK concat + linear ----
    k_gemm_cat2<<<gemm_blocks, 128>>>(x, Wl, bl, out, n);
}